// round 7
// baseline (speedup 1.0000x reference)
#include <cuda_runtime.h>
#include <cuda_bf16.h>
#include <math.h>

// RNNTAlignDistillLoss — B=8, T=256, U=64, V=1024.
// Inputs: d_in[0]=logits f32[B,T,U,V], d_in[1]=ys (unused),
//         d_in[2]=soft_labels f32[B,U,V], d_in[3]=aligns i32[B,U],
//         d_in[4]=xlens (unused), d_in[5]=ylens i32[B].
// Output: scalar f32 loss.
//
// loss_b = (Σ s·x − log(Σ e^x)) / ylen   (Σs = 1 over full V),
// loss = −Σ_b loss_b / B.
//
// Converged form (best measured: 6.528 µs wallclock, twice):
// one CTA, 8 warps, warp b handles batch b; depth-2 index chain via
// speculative aligns-row load; single fused interleaved pass; dual-chain
// warp reduction; one __syncthreads; 8-way shuffle combine in warp 0.

#define B_ 8
#define T_ 256
#define U_ 64
#define V_ 1024
#define LN2 0.6931471805599453f

__global__ __launch_bounds__(256, 1)
void rnnt_align_distill_loss_kernel(const float* __restrict__ logits,
                                    const float* __restrict__ soft_labels,
                                    const int*   __restrict__ aligns,
                                    const int*   __restrict__ ylens,
                                    float*       __restrict__ out)
{
    const int b    = threadIdx.x >> 5;   // warp id = batch element (0..7)
    const int lane = threadIdx.x & 31;

    __shared__ float sm_loss[B_];

    // --- depth-1 index loads (independent, overlap) -------------------------
    const int  ylen = ylens[b];
    const int2 arow = ((const int2*)(aligns + b * U_))[lane];  // full aligns row

    const int u  = ylen - 1;
    const int sx = __shfl_sync(0xFFFFFFFFu, arow.x, u >> 1);
    const int sy = __shfl_sync(0xFFFFFFFFu, arow.y, u >> 1);
    const int t  = (u & 1) ? sy : sx;

    const float4* __restrict__ sel = (const float4*)(logits +
                        (((size_t)b * T_ + t) * U_ + u) * V_);
    const float4* __restrict__ sl  = (const float4*)(soft_labels +
                        ((size_t)b * U_ + u) * V_);

    // --- single fused interleaved pass: Σ e^x and Σ s·x ---------------------
    float se  = 0.0f;
    float dot = 0.0f;
    #pragma unroll
    for (int k = 0; k < 8; k++) {
        const float4 x = sel[lane + k * 32];
        const float4 s = sl [lane + k * 32];
        se  += __expf(x.x) + __expf(x.y) + __expf(x.z) + __expf(x.w);
        dot += s.x * x.x + s.y * x.y + s.z * x.z + s.w * x.w;
    }

    // --- dual-chain warp reduction (independent, overlap) --------------------
    #pragma unroll
    for (int off = 16; off > 0; off >>= 1) {
        se  += __shfl_xor_sync(0xFFFFFFFFu, se,  off);
        dot += __shfl_xor_sync(0xFFFFFFFFu, dot, off);
    }

    if (lane == 0)
        sm_loss[b] = (dot - __log2f(se) * LN2) / (float)ylen;
    __syncthreads();

    // --- final 8-way combine in warp 0 ---------------------------------------
    if (threadIdx.x < 32) {
        float v = (lane < B_) ? sm_loss[lane] : 0.0f;
        #pragma unroll
        for (int off = 4; off > 0; off >>= 1)
            v += __shfl_xor_sync(0xFFFFFFFFu, v, off);
        if (lane == 0) out[0] = -v * (1.0f / (float)B_);
    }
}

extern "C" void kernel_launch(void* const* d_in, const int* in_sizes, int n_in,
                              void* d_out, int out_size)
{
    const float* logits      = (const float*)d_in[0];
    const float* soft_labels = (const float*)d_in[2];
    const int*   aligns      = (const int*)d_in[3];
    const int*   ylens       = (const int*)d_in[5];
    float*       out         = (float*)d_out;

    rnnt_align_distill_loss_kernel<<<1, 256>>>(logits, soft_labels, aligns, ylens, out);
}

// round 8
// speedup vs baseline: 1.0385x; 1.0385x over previous
#include <cuda_runtime.h>
#include <cuda_bf16.h>
#include <math.h>

// RNNTAlignDistillLoss — B=8, T=256, U=64, V=1024.
// Inputs: d_in[0]=logits f32[B,T,U,V], d_in[1]=ys (unused),
//         d_in[2]=soft_labels f32[B,U,V], d_in[3]=aligns i32[B,U],
//         d_in[4]=xlens (unused), d_in[5]=ylens i32[B].
// Output: scalar f32 loss.
//
// loss_b = (Σ s·x − log(Σ e^x)) / ylen   (Σs = 1 over full V),
// loss = −Σ_b loss_b / B.
//
// One CTA, 8 warps; warp b handles batch b. Dependency scheduling:
//   ylens[b]  ──► u ──► soft-label loads (issued BEFORE the t-select)
//   aligns row ─┘  └─► shuffle-select t ──► logits loads (interleaved w/ compute)
// so the sl burst is in flight during the shuffle chain and the sel burst.

#define B_ 8
#define T_ 256
#define U_ 64
#define V_ 1024
#define LN2 0.6931471805599453f

__global__ __launch_bounds__(256, 1)
void rnnt_align_distill_loss_kernel(const float* __restrict__ logits,
                                    const float* __restrict__ soft_labels,
                                    const int*   __restrict__ aligns,
                                    const int*   __restrict__ ylens,
                                    float*       __restrict__ out)
{
    const int b    = threadIdx.x >> 5;   // warp id = batch element (0..7)
    const int lane = threadIdx.x & 31;

    __shared__ float sm_loss[B_];

    // --- depth-1 index loads (independent, overlap) -------------------------
    const int  ylen = ylens[b];
    const int2 arow = ((const int2*)(aligns + b * U_))[lane];  // full aligns row

    const int u = ylen - 1;

    // --- soft-label loads: address ready as soon as ylen lands ---------------
    const float4* __restrict__ sl = (const float4*)(soft_labels +
                        ((size_t)b * U_ + u) * V_);
    float4 s[8];
    #pragma unroll
    for (int k = 0; k < 8; k++) s[k] = sl[lane + k * 32];

    // --- select t = aligns[b][u] via shuffle (overlaps sl in-flight) ---------
    const int sx = __shfl_sync(0xFFFFFFFFu, arow.x, u >> 1);
    const int sy = __shfl_sync(0xFFFFFFFFu, arow.y, u >> 1);
    const int t  = (u & 1) ? sy : sx;

    const float4* __restrict__ sel = (const float4*)(logits +
                        (((size_t)b * T_ + t) * U_ + u) * V_);

    // --- fused pass: load logits, Σ e^x and Σ s·x ----------------------------
    float se  = 0.0f;
    float dot = 0.0f;
    #pragma unroll
    for (int k = 0; k < 8; k++) {
        const float4 x = sel[lane + k * 32];
        se  += __expf(x.x) + __expf(x.y) + __expf(x.z) + __expf(x.w);
        dot += s[k].x * x.x + s[k].y * x.y + s[k].z * x.z + s[k].w * x.w;
    }

    // --- dual-chain warp reduction (independent, overlap) --------------------
    #pragma unroll
    for (int off = 16; off > 0; off >>= 1) {
        se  += __shfl_xor_sync(0xFFFFFFFFu, se,  off);
        dot += __shfl_xor_sync(0xFFFFFFFFu, dot, off);
    }

    if (lane == 0)
        sm_loss[b] = (dot - __log2f(se) * LN2) / (float)ylen;
    __syncthreads();

    // --- final 8-way combine in warp 0 ---------------------------------------
    if (threadIdx.x < 32) {
        float v = (lane < B_) ? sm_loss[lane] : 0.0f;
        #pragma unroll
        for (int off = 4; off > 0; off >>= 1)
            v += __shfl_xor_sync(0xFFFFFFFFu, v, off);
        if (lane == 0) out[0] = -v * (1.0f / (float)B_);
    }
}

extern "C" void kernel_launch(void* const* d_in, const int* in_sizes, int n_in,
                              void* d_out, int out_size)
{
    const float* logits      = (const float*)d_in[0];
    const float* soft_labels = (const float*)d_in[2];
    const int*   aligns      = (const int*)d_in[3];
    const int*   ylens       = (const int*)d_in[5];
    float*       out         = (float*)d_out;

    rnnt_align_distill_loss_kernel<<<1, 256>>>(logits, soft_labels, aligns, ylens, out);
}

// round 9
// speedup vs baseline: 1.0693x; 1.0297x over previous
#include <cuda_runtime.h>
#include <cuda_bf16.h>
#include <math.h>

// RNNTAlignDistillLoss — B=8, T=256, U=64, V=1024.
// Inputs: d_in[0]=logits f32[B,T,U,V], d_in[1]=ys (unused),
//         d_in[2]=soft_labels f32[B,U,V], d_in[3]=aligns i32[B,U],
//         d_in[4]=xlens (unused), d_in[5]=ylens i32[B].
// Output: scalar f32 loss.
//
// loss_b = (Σ s·x − log(Σ e^x)) / ylen   (Σs = 1 over full V),
// loss = −Σ_b loss_b / B.
//
// Converged kernel (session-best profiled dur 4.86 µs):
// one CTA, 8 warps; warp b handles batch b. Dependency scheduling:
//   ylens[b]  ──► u ──► soft-label loads (issued BEFORE the t-select)
//   aligns row ─┘  └─► shuffle-select t ──► logits loads (interleaved w/ compute)
// so the sl burst is in flight during the shuffle chain and the sel burst.

#define B_ 8
#define T_ 256
#define U_ 64
#define V_ 1024
#define LN2 0.6931471805599453f

__global__ __launch_bounds__(256, 1)
void rnnt_align_distill_loss_kernel(const float* __restrict__ logits,
                                    const float* __restrict__ soft_labels,
                                    const int*   __restrict__ aligns,
                                    const int*   __restrict__ ylens,
                                    float*       __restrict__ out)
{
    const int b    = threadIdx.x >> 5;   // warp id = batch element (0..7)
    const int lane = threadIdx.x & 31;

    __shared__ float sm_loss[B_];

    // --- depth-1 index loads (independent, overlap) -------------------------
    const int  ylen = ylens[b];
    const int2 arow = ((const int2*)(aligns + b * U_))[lane];  // full aligns row

    const int u = ylen - 1;

    // --- soft-label loads: address ready as soon as ylen lands ---------------
    const float4* __restrict__ sl = (const float4*)(soft_labels +
                        ((size_t)b * U_ + u) * V_);
    float4 s[8];
    #pragma unroll
    for (int k = 0; k < 8; k++) s[k] = sl[lane + k * 32];

    // --- select t = aligns[b][u] via shuffle (overlaps sl in-flight) ---------
    const int sx = __shfl_sync(0xFFFFFFFFu, arow.x, u >> 1);
    const int sy = __shfl_sync(0xFFFFFFFFu, arow.y, u >> 1);
    const int t  = (u & 1) ? sy : sx;

    const float4* __restrict__ sel = (const float4*)(logits +
                        (((size_t)b * T_ + t) * U_ + u) * V_);

    // --- fused pass: load logits, Σ e^x and Σ s·x ----------------------------
    float se  = 0.0f;
    float dot = 0.0f;
    #pragma unroll
    for (int k = 0; k < 8; k++) {
        const float4 x = sel[lane + k * 32];
        se  += __expf(x.x) + __expf(x.y) + __expf(x.z) + __expf(x.w);
        dot += s[k].x * x.x + s[k].y * x.y + s[k].z * x.z + s[k].w * x.w;
    }

    // --- dual-chain warp reduction (independent, overlap) --------------------
    #pragma unroll
    for (int off = 16; off > 0; off >>= 1) {
        se  += __shfl_xor_sync(0xFFFFFFFFu, se,  off);
        dot += __shfl_xor_sync(0xFFFFFFFFu, dot, off);
    }

    if (lane == 0)
        sm_loss[b] = __fdividef(dot - __log2f(se) * LN2, (float)ylen);
    __syncthreads();

    // --- final 8-way combine in warp 0 ---------------------------------------
    if (threadIdx.x < 32) {
        float v = (lane < B_) ? sm_loss[lane] : 0.0f;
        #pragma unroll
        for (int off = 4; off > 0; off >>= 1)
            v += __shfl_xor_sync(0xFFFFFFFFu, v, off);
        if (lane == 0) out[0] = v * (-1.0f / (float)B_);
    }
}

extern "C" void kernel_launch(void* const* d_in, const int* in_sizes, int n_in,
                              void* d_out, int out_size)
{
    const float* logits      = (const float*)d_in[0];
    const float* soft_labels = (const float*)d_in[2];
    const int*   aligns      = (const int*)d_in[3];
    const int*   ylens       = (const int*)d_in[5];
    float*       out         = (float*)d_out;

    rnnt_align_distill_loss_kernel<<<1, 256>>>(logits, soft_labels, aligns, ylens, out);
}